// round 14
// baseline (speedup 1.0000x reference)
#include <cuda_runtime.h>

// HybridODENN: B=1024, T=256, H=128, 3 hidden layers, S=6
#define B_DIM 1024
#define T_DIM 256
#define H_DIM 128
#define S_DIM 6
#define ROWS 8                    // array sizing (pad row 7)
#define NROWS 7                   // real rows per CTA
#define GRID 147                  // 146 x 7 + 1 x 2 = 1024
#define NTHREADS 512
#define HSTRIDE 132               // 132 mod 32 = 4 -> all 8 row offsets distinct banks

// ODE constants
#define C_A_GI 0.01f
#define C_K_I  0.1f
#define C_RHO  0.05f
#define C_EMAX 2.0f
#define C_EC50 5.0f
#define C_VMAX 1.0f
#define C_KM   100.0f
#define C_KL   0.2f

typedef unsigned long long ull;

#define FFMA2(d, a, b) asm("fma.rn.f32x2 %0, %1, %2, %0;" : "+l"(d) : "l"(a), "l"(b))

__device__ __forceinline__ ull add2(ull a, ull b) {
    ull d; asm("add.rn.f32x2 %0, %1, %2;" : "=l"(d) : "l"(a), "l"(b)); return d;
}
__device__ __forceinline__ float2 unpack2(ull v) {
    float lo, hi;
    asm("mov.b64 {%0, %1}, %2;" : "=f"(lo), "=f"(hi) : "l"(v));
    return make_float2(lo, hi);
}
__device__ __forceinline__ ull dup2f(float x) {
    ull d; asm("mov.b64 %0, {%1, %1};" : "=l"(d) : "f"(x)); return d;
}
// fast tanh: 1 - 2/(e^{2x}+1), ~1e-7 rel err
__device__ __forceinline__ float tanh_fast(float x) {
    float e;
    asm("ex2.approx.f32 %0, %1;" : "=f"(e) : "f"(x * 2.8853900817779268f));
    float r;
    asm("rcp.approx.f32 %0, %1;" : "=f"(r) : "f"(e + 1.0f));
    return fmaf(-2.0f, r, 1.0f);
}
// h column swizzle: chunk ck = c>>2 -> ck ^ (ck>>3), keep (c&3)
__device__ __forceinline__ int hswz(int c) {
    int ck = c >> 2;
    int ckp = ck ^ (ck >> 3);
    return ckp * 4 + (c & 3);
}

struct __align__(16) Smem {
    // W_h[l][k][ g'*4 + (c&3) ], g' = (c>>2) ^ ((k>>3)&15)
    float W_h[3][H_DIM][H_DIM];   // 192 KB
    float W_in[9][H_DIM];
    float W_out_t[S_DIM][H_DIM];
    float b_in[H_DIM];
    float b_h[3][H_DIM];
    float b_out[8];
    float h[2][ROWS * HSTRIDE];   // swizzled cols + padded rows
    float y[ROWS][S_DIM];
    float acc[ROWS][S_DIM];
};

__device__ __forceinline__ float ode_comp(int o, const float* y, float m) {
    float G = y[0], I = y[1], N = y[2], L = y[3], GE = y[4], F = y[5];
    switch (o) {
        case 0: return -C_A_GI * I * G + C_RHO * GE;
        case 1: return __fdividef(C_VMAX * G, C_KM + G)
                       * (1.0f + C_EMAX * __fdividef(L, C_EC50 + L)) - C_K_I * I;
        case 2: return -C_RHO * N;
        case 3: return C_RHO * GE - C_KL * L;
        case 4: return m - C_RHO * GE;
        default: return -C_A_GI * I * F;
    }
}

// fused input layer (r11 scalar version): warp owns row r; lane -> cols [lane*4, lane*4+4)
__device__ __forceinline__ void input_row(Smem* s, int r, int lane,
                                          float y0, float y1, float y2,
                                          float y3, float y4, float y5,
                                          float ts, float vs)
{
    int jb = lane * 4;
    int so = r * HSTRIDE + ((lane ^ (lane >> 3)) * 4);   // hswz of chunk=lane
    float4 bb = *reinterpret_cast<const float4*>(&s->b_in[jb]);
    float4 q0 = *reinterpret_cast<const float4*>(&s->W_in[0][jb]);
    float4 q1 = *reinterpret_cast<const float4*>(&s->W_in[1][jb]);
    float4 q2 = *reinterpret_cast<const float4*>(&s->W_in[2][jb]);
    float4 q3 = *reinterpret_cast<const float4*>(&s->W_in[3][jb]);
    float4 q4 = *reinterpret_cast<const float4*>(&s->W_in[4][jb]);
    float4 q5 = *reinterpret_cast<const float4*>(&s->W_in[5][jb]);
    float4 q6 = *reinterpret_cast<const float4*>(&s->W_in[6][jb]);
    float4 q7 = *reinterpret_cast<const float4*>(&s->W_in[7][jb]);
    float4 q8 = *reinterpret_cast<const float4*>(&s->W_in[8][jb]);
    float4 a;
    a.x = bb.x + ts*q0.x + y0*q1.x + y1*q2.x + y2*q3.x + y3*q4.x + y4*q5.x + y5*q6.x + y3*q7.x + vs*q8.x;
    a.y = bb.y + ts*q0.y + y0*q1.y + y1*q2.y + y2*q3.y + y3*q4.y + y4*q5.y + y5*q6.y + y3*q7.y + vs*q8.y;
    a.z = bb.z + ts*q0.z + y0*q1.z + y1*q2.z + y2*q3.z + y3*q4.z + y4*q5.z + y5*q6.z + y3*q7.z + vs*q8.z;
    a.w = bb.w + ts*q0.w + y0*q1.w + y1*q2.w + y2*q3.w + y3*q4.w + y4*q5.w + y5*q6.w + y3*q7.w + vs*q8.w;
    float4 o4;
    o4.x = tanh_fast(a.x); o4.y = tanh_fast(a.y);
    o4.z = tanh_fast(a.z); o4.w = tanh_fast(a.w);
    *reinterpret_cast<float4*>(&s->h[0][so]) = o4;
}

__global__ void __launch_bounds__(NTHREADS, 1)
hybrid_ode_kernel(const float* __restrict__ init,
                  const float* __restrict__ t_span,
                  const float* __restrict__ meal,
                  const float* __restrict__ tvns,
                  const float* __restrict__ gW_in,
                  const float* __restrict__ gb_in,
                  const float* __restrict__ gW_h,
                  const float* __restrict__ gb_h,
                  const float* __restrict__ gW_out,
                  const float* __restrict__ gb_out,
                  float* __restrict__ out)
{
    extern __shared__ __align__(16) char smem_raw[];
    Smem* s = reinterpret_cast<Smem*>(smem_raw);

    const int tid  = threadIdx.x;
    const int cta  = blockIdx.x;
    const int base = cta * NROWS;
    const int nr   = (B_DIM - base < NROWS) ? (B_DIM - base) : NROWS;

    // ---- one-time weight staging (W_h col-group XOR swizzle) ----
    for (int i = tid; i < 3 * H_DIM * H_DIM; i += NTHREADS) {
        int l = i >> 14;
        int rem = i & 16383;
        int k = rem >> 7, c = rem & 127;
        int gp = (c >> 2) ^ ((k >> 3) & 15);
        s->W_h[l][k][gp * 4 + (c & 3)] = gW_h[i];
    }
    for (int i = tid; i < 9 * H_DIM; i += NTHREADS) (&s->W_in[0][0])[i] = gW_in[i];
    for (int i = tid; i < H_DIM; i += NTHREADS) s->b_in[i] = gb_in[i];
    for (int i = tid; i < 3 * H_DIM; i += NTHREADS) (&s->b_h[0][0])[i] = gb_h[i];
    for (int i = tid; i < H_DIM * S_DIM; i += NTHREADS) {
        int k = i / S_DIM, o = i % S_DIM;
        s->W_out_t[o][k] = gW_out[i];
    }
    if (tid < S_DIM) (&s->b_out[0])[tid] = gb_out[tid];

    // ---- GEMM mapping (r10/r11-proven) ----
    const int w    = tid >> 5;
    const int lane = tid & 31;
    const int ks   = lane & 15;
    const int cg   = lane >> 4;
    const int c0   = w * 8 + cg * 4;
    const int gexp = (((w << 1) + cg) ^ ks) << 2;
    int hco0, hco1;
    {
        int ck0 = 2 * ks, ck1 = 2 * ks + 1;
        hco0 = (ck0 ^ (ck0 >> 3)) * 4;
        hco1 = (ck1 ^ (ck1 >> 3)) * 4;
    }
    const int frow = ((ks >> 3) & 1) * 4 + ((ks >> 2) & 1) * 2 + ((ks >> 1) & 1);
    const int fcol = c0 + 2 * (ks & 1);
    const int fco  = frow * HSTRIDE + hswz(fcol);
    const bool b3 = (ks & 8) != 0, b2 = (ks & 4) != 0, b1 = (ks & 2) != 0, b0 = (ks & 1) != 0;
    const int sw0 = hswz(lane), sw1 = hswz(lane + 32), sw2 = hswz(lane + 64), sw3 = hswz(lane + 96);

    // ---- register-resident ycur (warp w < NROWS owns batch row w) ----
    float yc0 = 0.f, yc1 = 0.f, yc2 = 0.f, yc3 = 0.f, yc4 = 0.f, yc5 = 0.f;
    if (w < NROWS) {
        int rr = (w < nr) ? w : 0;
        const float* ip = init + (size_t)(base + rr) * S_DIM;
        yc0 = ip[0]; yc1 = ip[1]; yc2 = ip[2];
        yc3 = ip[3]; yc4 = ip[4]; yc5 = ip[5];
        if (lane == 0) {
            s->y[w][0] = yc0; s->y[w][1] = yc1; s->y[w][2] = yc2;
            s->y[w][3] = yc3; s->y[w][4] = yc4; s->y[w][5] = yc5;
            s->acc[w][0] = yc0; s->acc[w][1] = yc1; s->acc[w][2] = yc2;
            s->acc[w][3] = yc3; s->acc[w][4] = yc4; s->acc[w][5] = yc5;
            if (w < nr) {
                float* op = out + (size_t)(base + w) * T_DIM * S_DIM;
                *reinterpret_cast<float2*>(op)     = make_float2(yc0, yc1);
                *reinterpret_cast<float2*>(op + 2) = make_float2(yc2, yc3);
                *reinterpret_cast<float2*>(op + 4) = make_float2(yc4, yc5);
            }
        }
    }
    __syncthreads();

    // ---- persistent W registers: k-chunk 0, all 3 layers ----
    ulonglong2 wp0[4], wp1[4], wp2[4];
    #pragma unroll
    for (int i = 0; i < 4; ++i) {
        wp0[i] = *reinterpret_cast<const ulonglong2*>(&s->W_h[0][ks * 8 + i][0] + gexp);
        wp1[i] = *reinterpret_cast<const ulonglong2*>(&s->W_h[1][ks * 8 + i][0] + gexp);
        wp2[i] = *reinterpret_cast<const ulonglong2*>(&s->W_h[2][ks * 8 + i][0] + gexp);
    }

    for (int t = 0; t < T_DIM - 1; ++t) {
        const float T0 = t_span[t], T1 = t_span[t + 1];
        const float dt = T1 - T0;
        const float tm = T0 + 0.5f * dt;
        const float dt6 = dt * (1.0f / 6.0f), dt3 = dt * (1.0f / 3.0f);

        float m0 = 0.f, mm = 0.f, m1 = 0.f, v1 = 0.f, vm = 0.f;
        if (w < NROWS) {
            int rr = (w < nr) ? w : 0;
            size_t ri = (size_t)(base + rr) * T_DIM + t;
            float M0 = meal[ri], M1 = meal[ri + 1];
            float V0 = tvns[ri], V1 = tvns[ri + 1];
            m0 = M0; m1 = M1; mm = 0.5f * (M0 + M1);
            v1 = V1; vm = 0.5f * (V0 + V1);
            input_row(s, w, lane, yc0, yc1, yc2, yc3, yc4, yc5, T0, V0);
        }
        __syncthreads();

        #pragma unroll 1
        for (int st = 0; st < 4; ++st) {
            // ---- 3 hidden layers (r11 GEMM: per-layer wv load, wp persistent) ----
            #pragma unroll
            for (int L = 0; L < 3; ++L) {
                const float* hin  = s->h[L & 1];
                float*       hout = s->h[(L & 1) ^ 1];
                const float* wbase = &s->W_h[L][ks * 8][0] + gexp;

                ulonglong2 wv[4];
                #pragma unroll
                for (int i = 0; i < 4; ++i)
                    wv[i] = *reinterpret_cast<const ulonglong2*>(wbase + (4 + i) * H_DIM);

                ull acc[8][2];
                #pragma unroll
                for (int r = 0; r < 8; ++r) { acc[r][0] = 0ull; acc[r][1] = 0ull; }

                #pragma unroll
                for (int r = 0; r < NROWS; ++r) {
                    float4 ha = *reinterpret_cast<const float4*>(hin + r * HSTRIDE + hco0);
                    float4 hb = *reinterpret_cast<const float4*>(hin + r * HSTRIDE + hco1);
                    ull d;
                    if (L == 0) {
                        d = dup2f(ha.x); FFMA2(acc[r][0], d, wp0[0].x); FFMA2(acc[r][1], d, wp0[0].y);
                        d = dup2f(ha.y); FFMA2(acc[r][0], d, wp0[1].x); FFMA2(acc[r][1], d, wp0[1].y);
                        d = dup2f(ha.z); FFMA2(acc[r][0], d, wp0[2].x); FFMA2(acc[r][1], d, wp0[2].y);
                        d = dup2f(ha.w); FFMA2(acc[r][0], d, wp0[3].x); FFMA2(acc[r][1], d, wp0[3].y);
                    } else if (L == 1) {
                        d = dup2f(ha.x); FFMA2(acc[r][0], d, wp1[0].x); FFMA2(acc[r][1], d, wp1[0].y);
                        d = dup2f(ha.y); FFMA2(acc[r][0], d, wp1[1].x); FFMA2(acc[r][1], d, wp1[1].y);
                        d = dup2f(ha.z); FFMA2(acc[r][0], d, wp1[2].x); FFMA2(acc[r][1], d, wp1[2].y);
                        d = dup2f(ha.w); FFMA2(acc[r][0], d, wp1[3].x); FFMA2(acc[r][1], d, wp1[3].y);
                    } else {
                        d = dup2f(ha.x); FFMA2(acc[r][0], d, wp2[0].x); FFMA2(acc[r][1], d, wp2[0].y);
                        d = dup2f(ha.y); FFMA2(acc[r][0], d, wp2[1].x); FFMA2(acc[r][1], d, wp2[1].y);
                        d = dup2f(ha.z); FFMA2(acc[r][0], d, wp2[2].x); FFMA2(acc[r][1], d, wp2[2].y);
                        d = dup2f(ha.w); FFMA2(acc[r][0], d, wp2[3].x); FFMA2(acc[r][1], d, wp2[3].y);
                    }
                    d = dup2f(hb.x); FFMA2(acc[r][0], d, wv[0].x); FFMA2(acc[r][1], d, wv[0].y);
                    d = dup2f(hb.y); FFMA2(acc[r][0], d, wv[1].x); FFMA2(acc[r][1], d, wv[1].y);
                    d = dup2f(hb.z); FFMA2(acc[r][0], d, wv[2].x); FFMA2(acc[r][1], d, wv[2].y);
                    d = dup2f(hb.w); FFMA2(acc[r][0], d, wv[3].x); FFMA2(acc[r][1], d, wv[3].y);
                }

                // ---- 4-round send-select fold over 16-way k-split (acc[7] = 0) ----
                #pragma unroll
                for (int i = 0; i < 4; ++i)
                    #pragma unroll
                    for (int c = 0; c < 2; ++c) {
                        ull snd = b3 ? acc[i][c] : acc[i + 4][c];
                        ull rcv = __shfl_xor_sync(0xffffffffu, snd, 8);
                        ull kp  = b3 ? acc[i + 4][c] : acc[i][c];
                        acc[i][c] = add2(kp, rcv);
                    }
                #pragma unroll
                for (int i = 0; i < 2; ++i)
                    #pragma unroll
                    for (int c = 0; c < 2; ++c) {
                        ull snd = b2 ? acc[i][c] : acc[i + 2][c];
                        ull rcv = __shfl_xor_sync(0xffffffffu, snd, 4);
                        ull kp  = b2 ? acc[i + 2][c] : acc[i][c];
                        acc[i][c] = add2(kp, rcv);
                    }
                #pragma unroll
                for (int c = 0; c < 2; ++c) {
                    ull snd = b1 ? acc[0][c] : acc[1][c];
                    ull rcv = __shfl_xor_sync(0xffffffffu, snd, 2);
                    ull kp  = b1 ? acc[1][c] : acc[0][c];
                    acc[0][c] = add2(kp, rcv);
                }
                ull fin;
                {
                    ull snd = b0 ? acc[0][0] : acc[0][1];
                    ull rcv = __shfl_xor_sync(0xffffffffu, snd, 1);
                    ull kp  = b0 ? acc[0][1] : acc[0][0];
                    fin = add2(kp, rcv);
                }

                float2 vv = unpack2(fin);
                float2 bb = *reinterpret_cast<const float2*>(&s->b_h[L][fcol]);
                float2 rr;
                rr.x = tanh_fast(vv.x + bb.x);
                rr.y = tanh_fast(vv.y + bb.y);
                *reinterpret_cast<float2*>(&hout[fco]) = rr;
                __syncthreads();
            }

            // ---- fused epilogue + next-stage input (warps 0..6; r11 scalar dots) ----
            if (w < NROWS) {
                const float* hr = &s->h[1][w * HSTRIDE];
                float hv0 = hr[sw0], hv1 = hr[sw1], hv2 = hr[sw2], hv3 = hr[sw3];
                float dots[S_DIM];
                #pragma unroll
                for (int o = 0; o < S_DIM; ++o) {
                    float p = hv0 * s->W_out_t[o][lane]
                            + hv1 * s->W_out_t[o][lane + 32]
                            + hv2 * s->W_out_t[o][lane + 64]
                            + hv3 * s->W_out_t[o][lane + 96];
                    #pragma unroll
                    for (int off = 16; off; off >>= 1)
                        p += __shfl_xor_sync(0xffffffffu, p, off);  // allreduce: valid on all lanes
                    dots[o] = p;
                }
                float msel = (st == 0) ? m0 : ((st == 3) ? m1 : mm);
                float wg   = (st == 0 || st == 3) ? dt6 : dt3;
                float yca[S_DIM] = {yc0, yc1, yc2, yc3, yc4, yc5};
                float nyc[S_DIM];
                if (st < 3) {
                    float cn = (st < 2) ? 0.5f * dt : dt;
                    #pragma unroll
                    for (int o = 0; o < S_DIM; ++o) {
                        float kv = dots[o] + s->b_out[o] + ode_comp(o, yca, msel);
                        float av = s->acc[w][o] + wg * kv;
                        if (lane == 0) s->acc[w][o] = av;
                        nyc[o] = s->y[w][o] + cn * kv;
                    }
                } else {
                    #pragma unroll
                    for (int o = 0; o < S_DIM; ++o) {
                        float kv = dots[o] + s->b_out[o] + ode_comp(o, yca, msel);
                        float av = s->acc[w][o] + wg * kv;
                        nyc[o] = av;
                        if (lane == 0) {
                            s->acc[w][o] = av;
                            s->y[w][o] = av;
                        }
                    }
                    if (lane == 0 && w < nr) {
                        float* op = out + (size_t)(base + w) * T_DIM * S_DIM
                                        + (size_t)(t + 1) * S_DIM;
                        *reinterpret_cast<float2*>(op)     = make_float2(nyc[0], nyc[1]);
                        *reinterpret_cast<float2*>(op + 2) = make_float2(nyc[2], nyc[3]);
                        *reinterpret_cast<float2*>(op + 4) = make_float2(nyc[4], nyc[5]);
                    }
                }
                yc0 = nyc[0]; yc1 = nyc[1]; yc2 = nyc[2];
                yc3 = nyc[3]; yc4 = nyc[4]; yc5 = nyc[5];
                if (st < 3) {
                    float ts_n = (st == 2) ? T1 : tm;
                    float vs_n = (st == 2) ? v1 : vm;
                    input_row(s, w, lane, yc0, yc1, yc2, yc3, yc4, yc5, ts_n, vs_n);
                }
            }
            __syncthreads();
        } // stages
    } // steps
}

extern "C" void kernel_launch(void* const* d_in, const int* in_sizes, int n_in,
                              void* d_out, int out_size) {
    const float* init   = (const float*)d_in[0];
    const float* t_span = (const float*)d_in[1];
    const float* meal   = (const float*)d_in[2];
    const float* tvns   = (const float*)d_in[3];
    const float* W_in   = (const float*)d_in[4];
    const float* b_in   = (const float*)d_in[5];
    const float* W_h    = (const float*)d_in[6];
    const float* b_h    = (const float*)d_in[7];
    const float* W_out  = (const float*)d_in[8];
    const float* b_out  = (const float*)d_in[9];
    float* out = (float*)d_out;

    const size_t smem_bytes = sizeof(Smem);  // ~205 KB
    cudaFuncSetAttribute(hybrid_ode_kernel,
                         cudaFuncAttributeMaxDynamicSharedMemorySize,
                         (int)smem_bytes);

    hybrid_ode_kernel<<<GRID, NTHREADS, smem_bytes>>>(
        init, t_span, meal, tvns, W_in, b_in, W_h, b_h, W_out, b_out, out);
}

// round 15
// speedup vs baseline: 1.0215x; 1.0215x over previous
#include <cuda_runtime.h>

// HybridODENN: B=1024, T=256, H=128, 3 hidden layers, S=6
#define B_DIM 1024
#define T_DIM 256
#define H_DIM 128
#define S_DIM 6
#define ROWS 8                    // array sizing (pad row 7)
#define NROWS 7                   // real rows per CTA
#define GRID 147                  // 146 x 7 + 1 x 2 = 1024
#define NTHREADS 512
#define HSTRIDE 136

// ODE constants
#define C_A_GI 0.01f
#define C_K_I  0.1f
#define C_RHO  0.05f
#define C_EMAX 2.0f
#define C_EC50 5.0f
#define C_VMAX 1.0f
#define C_KM   100.0f
#define C_KL   0.2f

typedef unsigned long long ull;

#define FFMA2(d, a, b) asm("fma.rn.f32x2 %0, %1, %2, %0;" : "+l"(d) : "l"(a), "l"(b))

__device__ __forceinline__ ull add2(ull a, ull b) {
    ull d; asm("add.rn.f32x2 %0, %1, %2;" : "=l"(d) : "l"(a), "l"(b)); return d;
}
__device__ __forceinline__ float2 unpack2(ull v) {
    float lo, hi;
    asm("mov.b64 {%0, %1}, %2;" : "=f"(lo), "=f"(hi) : "l"(v));
    return make_float2(lo, hi);
}
__device__ __forceinline__ ull dup2f(float x) {
    ull d; asm("mov.b64 %0, {%1, %1};" : "=l"(d) : "f"(x)); return d;
}
// fast tanh: 1 - 2/(e^{2x}+1), ~1e-7 rel err
__device__ __forceinline__ float tanh_fast(float x) {
    float e;
    asm("ex2.approx.f32 %0, %1;" : "=f"(e) : "f"(x * 2.8853900817779268f));
    float r;
    asm("rcp.approx.f32 %0, %1;" : "=f"(r) : "f"(e + 1.0f));
    return fmaf(-2.0f, r, 1.0f);
}
// h column swizzle: chunk ck = c>>2 -> ck ^ (ck>>3), keep (c&3)
__device__ __forceinline__ int hswz(int c) {
    int ck = c >> 2;
    int ckp = ck ^ (ck >> 3);
    return ckp * 4 + (c & 3);
}

struct __align__(16) Smem {
    // W_h[l][k][ g'*4 + (c&3) ], g' = (c>>2) ^ ((k>>3)&15)
    float W_h[3][H_DIM][H_DIM];   // 192 KB
    float W_in[9][H_DIM];         // row 4 holds W_in[4]+W_in[7] (y3 appears twice)
    float W_out_t[S_DIM][H_DIM];
    float b_in[H_DIM];
    float b_h[3][H_DIM];
    float b_out[8];
    float h[2][ROWS * HSTRIDE];   // swizzled cols + padded rows
    float y[ROWS][S_DIM];
    float acc[ROWS][S_DIM];
};

__device__ __forceinline__ float ode_comp(int o, const float* y, float m) {
    float G = y[0], I = y[1], N = y[2], L = y[3], GE = y[4], F = y[5];
    switch (o) {
        case 0: return -C_A_GI * I * G + C_RHO * GE;
        case 1: return __fdividef(C_VMAX * G, C_KM + G)
                       * (1.0f + C_EMAX * __fdividef(L, C_EC50 + L)) - C_K_I * I;
        case 2: return -C_RHO * N;
        case 3: return C_RHO * GE - C_KL * L;
        case 4: return m - C_RHO * GE;
        default: return -C_A_GI * I * F;
    }
}

// fused input layer: warp owns row r; lane computes cols [lane*4, lane*4+4)
// (W_in[4] has been pre-folded with W_in[7]: y3 coefficient combined)
__device__ __forceinline__ void input_row(Smem* s, int r, int lane,
                                          float y0, float y1, float y2,
                                          float y3, float y4, float y5,
                                          float ts, float vs)
{
    int jb = lane * 4;
    int so = r * HSTRIDE + ((lane ^ (lane >> 3)) * 4);   // hswz of chunk=lane
    float4 bb = *reinterpret_cast<const float4*>(&s->b_in[jb]);
    float4 q0 = *reinterpret_cast<const float4*>(&s->W_in[0][jb]);
    float4 q1 = *reinterpret_cast<const float4*>(&s->W_in[1][jb]);
    float4 q2 = *reinterpret_cast<const float4*>(&s->W_in[2][jb]);
    float4 q3 = *reinterpret_cast<const float4*>(&s->W_in[3][jb]);
    float4 q4 = *reinterpret_cast<const float4*>(&s->W_in[4][jb]);   // folded +W_in[7]
    float4 q5 = *reinterpret_cast<const float4*>(&s->W_in[5][jb]);
    float4 q6 = *reinterpret_cast<const float4*>(&s->W_in[6][jb]);
    float4 q8 = *reinterpret_cast<const float4*>(&s->W_in[8][jb]);
    float4 a;
    a.x = bb.x + ts*q0.x + y0*q1.x + y1*q2.x + y2*q3.x + y3*q4.x + y4*q5.x + y5*q6.x + vs*q8.x;
    a.y = bb.y + ts*q0.y + y0*q1.y + y1*q2.y + y2*q3.y + y3*q4.y + y4*q5.y + y5*q6.y + vs*q8.y;
    a.z = bb.z + ts*q0.z + y0*q1.z + y1*q2.z + y2*q3.z + y3*q4.z + y4*q5.z + y5*q6.z + vs*q8.z;
    a.w = bb.w + ts*q0.w + y0*q1.w + y1*q2.w + y2*q3.w + y3*q4.w + y4*q5.w + y5*q6.w + vs*q8.w;
    float4 o4;
    o4.x = tanh_fast(a.x); o4.y = tanh_fast(a.y);
    o4.z = tanh_fast(a.z); o4.w = tanh_fast(a.w);
    *reinterpret_cast<float4*>(&s->h[0][so]) = o4;
}

__global__ void __launch_bounds__(NTHREADS, 1)
hybrid_ode_kernel(const float* __restrict__ init,
                  const float* __restrict__ t_span,
                  const float* __restrict__ meal,
                  const float* __restrict__ tvns,
                  const float* __restrict__ gW_in,
                  const float* __restrict__ gb_in,
                  const float* __restrict__ gW_h,
                  const float* __restrict__ gb_h,
                  const float* __restrict__ gW_out,
                  const float* __restrict__ gb_out,
                  float* __restrict__ out)
{
    extern __shared__ __align__(16) char smem_raw[];
    Smem* s = reinterpret_cast<Smem*>(smem_raw);

    const int tid  = threadIdx.x;
    const int cta  = blockIdx.x;
    const int base = cta * NROWS;
    const int nr   = (B_DIM - base < NROWS) ? (B_DIM - base) : NROWS;

    // ---- one-time weight staging (W_h col-group XOR swizzle) ----
    for (int i = tid; i < 3 * H_DIM * H_DIM; i += NTHREADS) {
        int l = i >> 14;
        int rem = i & 16383;
        int k = rem >> 7, c = rem & 127;
        int gp = (c >> 2) ^ ((k >> 3) & 15);
        s->W_h[l][k][gp * 4 + (c & 3)] = gW_h[i];
    }
    for (int i = tid; i < 9 * H_DIM; i += NTHREADS) {
        int row = i >> 7;
        float v = gW_in[i];
        if (row == 4) v += gW_in[7 * H_DIM + (i & 127)];   // fold y3's second term
        (&s->W_in[0][0])[i] = v;
    }
    for (int i = tid; i < H_DIM; i += NTHREADS) s->b_in[i] = gb_in[i];
    for (int i = tid; i < 3 * H_DIM; i += NTHREADS) (&s->b_h[0][0])[i] = gb_h[i];
    for (int i = tid; i < H_DIM * S_DIM; i += NTHREADS) {
        int k = i / S_DIM, o = i % S_DIM;
        s->W_out_t[o][k] = gW_out[i];
    }
    if (tid < S_DIM) (&s->b_out[0])[tid] = gb_out[tid];

    // ---- GEMM mapping (r10/r11-proven) ----
    const int w    = tid >> 5;
    const int lane = tid & 31;
    const int ks   = lane & 15;
    const int cg   = lane >> 4;
    const int c0   = w * 8 + cg * 4;
    const int gexp = (((w << 1) + cg) ^ ks) << 2;
    int hco0, hco1;
    {
        int ck0 = 2 * ks, ck1 = 2 * ks + 1;
        hco0 = (ck0 ^ (ck0 >> 3)) * 4;
        hco1 = (ck1 ^ (ck1 >> 3)) * 4;
    }
    const int frow = ((ks >> 3) & 1) * 4 + ((ks >> 2) & 1) * 2 + ((ks >> 1) & 1);
    const int fcol = c0 + 2 * (ks & 1);
    const int fco  = frow * HSTRIDE + hswz(fcol);
    const bool b3 = (ks & 8) != 0, b2 = (ks & 4) != 0, b1 = (ks & 2) != 0, b0 = (ks & 1) != 0;
    const int sw0 = hswz(lane), sw1 = hswz(lane + 32), sw2 = hswz(lane + 64), sw3 = hswz(lane + 96);

    // ---- register-resident ycur (warp w < NROWS owns batch row w) ----
    float yc0 = 0.f, yc1 = 0.f, yc2 = 0.f, yc3 = 0.f, yc4 = 0.f, yc5 = 0.f;
    if (w < NROWS) {
        int rr = (w < nr) ? w : 0;
        const float* ip = init + (size_t)(base + rr) * S_DIM;
        yc0 = ip[0]; yc1 = ip[1]; yc2 = ip[2];
        yc3 = ip[3]; yc4 = ip[4]; yc5 = ip[5];
        if (lane == 0) {
            s->y[w][0] = yc0; s->y[w][1] = yc1; s->y[w][2] = yc2;
            s->y[w][3] = yc3; s->y[w][4] = yc4; s->y[w][5] = yc5;
            s->acc[w][0] = yc0; s->acc[w][1] = yc1; s->acc[w][2] = yc2;
            s->acc[w][3] = yc3; s->acc[w][4] = yc4; s->acc[w][5] = yc5;
            if (w < nr) {
                float* op = out + (size_t)(base + w) * T_DIM * S_DIM;
                op[0] = yc0; op[1] = yc1; op[2] = yc2;
                op[3] = yc3; op[4] = yc4; op[5] = yc5;
            }
        }
    }
    __syncthreads();

    // ---- persistent W registers: k-chunk 0, all 3 layers ----
    ulonglong2 wp0[4], wp1[4], wp2[4];
    #pragma unroll
    for (int i = 0; i < 4; ++i) {
        wp0[i] = *reinterpret_cast<const ulonglong2*>(&s->W_h[0][ks * 8 + i][0] + gexp);
        wp1[i] = *reinterpret_cast<const ulonglong2*>(&s->W_h[1][ks * 8 + i][0] + gexp);
        wp2[i] = *reinterpret_cast<const ulonglong2*>(&s->W_h[2][ks * 8 + i][0] + gexp);
    }

    for (int t = 0; t < T_DIM - 1; ++t) {
        const float T0 = t_span[t], T1 = t_span[t + 1];
        const float dt = T1 - T0;
        const float tm = T0 + 0.5f * dt;
        const float dt6 = dt * (1.0f / 6.0f), dt3 = dt * (1.0f / 3.0f);

        float m0 = 0.f, mm = 0.f, m1 = 0.f, v1 = 0.f, vm = 0.f;
        if (w < NROWS) {
            int rr = (w < nr) ? w : 0;
            size_t ri = (size_t)(base + rr) * T_DIM + t;
            float M0 = meal[ri], M1 = meal[ri + 1];
            float V0 = tvns[ri], V1 = tvns[ri + 1];
            m0 = M0; m1 = M1; mm = 0.5f * (M0 + M1);
            v1 = V1; vm = 0.5f * (V0 + V1);
            input_row(s, w, lane, yc0, yc1, yc2, yc3, yc4, yc5, T0, V0);
        }
        __syncthreads();

        #pragma unroll 1
        for (int st = 0; st < 4; ++st) {
            // ---- 3 hidden layers (r11 GEMM: per-layer wv load, wp persistent) ----
            #pragma unroll
            for (int L = 0; L < 3; ++L) {
                const float* hin  = s->h[L & 1];
                float*       hout = s->h[(L & 1) ^ 1];
                const float* wbase = &s->W_h[L][ks * 8][0] + gexp;

                ulonglong2 wv[4];
                #pragma unroll
                for (int i = 0; i < 4; ++i)
                    wv[i] = *reinterpret_cast<const ulonglong2*>(wbase + (4 + i) * H_DIM);

                ull acc[8][2];
                #pragma unroll
                for (int r = 0; r < 8; ++r) { acc[r][0] = 0ull; acc[r][1] = 0ull; }

                #pragma unroll
                for (int r = 0; r < NROWS; ++r) {
                    float4 ha = *reinterpret_cast<const float4*>(hin + r * HSTRIDE + hco0);
                    float4 hb = *reinterpret_cast<const float4*>(hin + r * HSTRIDE + hco1);
                    ull d;
                    if (L == 0) {
                        d = dup2f(ha.x); FFMA2(acc[r][0], d, wp0[0].x); FFMA2(acc[r][1], d, wp0[0].y);
                        d = dup2f(ha.y); FFMA2(acc[r][0], d, wp0[1].x); FFMA2(acc[r][1], d, wp0[1].y);
                        d = dup2f(ha.z); FFMA2(acc[r][0], d, wp0[2].x); FFMA2(acc[r][1], d, wp0[2].y);
                        d = dup2f(ha.w); FFMA2(acc[r][0], d, wp0[3].x); FFMA2(acc[r][1], d, wp0[3].y);
                    } else if (L == 1) {
                        d = dup2f(ha.x); FFMA2(acc[r][0], d, wp1[0].x); FFMA2(acc[r][1], d, wp1[0].y);
                        d = dup2f(ha.y); FFMA2(acc[r][0], d, wp1[1].x); FFMA2(acc[r][1], d, wp1[1].y);
                        d = dup2f(ha.z); FFMA2(acc[r][0], d, wp1[2].x); FFMA2(acc[r][1], d, wp1[2].y);
                        d = dup2f(ha.w); FFMA2(acc[r][0], d, wp1[3].x); FFMA2(acc[r][1], d, wp1[3].y);
                    } else {
                        d = dup2f(ha.x); FFMA2(acc[r][0], d, wp2[0].x); FFMA2(acc[r][1], d, wp2[0].y);
                        d = dup2f(ha.y); FFMA2(acc[r][0], d, wp2[1].x); FFMA2(acc[r][1], d, wp2[1].y);
                        d = dup2f(ha.z); FFMA2(acc[r][0], d, wp2[2].x); FFMA2(acc[r][1], d, wp2[2].y);
                        d = dup2f(ha.w); FFMA2(acc[r][0], d, wp2[3].x); FFMA2(acc[r][1], d, wp2[3].y);
                    }
                    d = dup2f(hb.x); FFMA2(acc[r][0], d, wv[0].x); FFMA2(acc[r][1], d, wv[0].y);
                    d = dup2f(hb.y); FFMA2(acc[r][0], d, wv[1].x); FFMA2(acc[r][1], d, wv[1].y);
                    d = dup2f(hb.z); FFMA2(acc[r][0], d, wv[2].x); FFMA2(acc[r][1], d, wv[2].y);
                    d = dup2f(hb.w); FFMA2(acc[r][0], d, wv[3].x); FFMA2(acc[r][1], d, wv[3].y);
                }

                // ---- 4-round send-select fold over 16-way k-split (acc[7] = 0) ----
                #pragma unroll
                for (int i = 0; i < 4; ++i)
                    #pragma unroll
                    for (int c = 0; c < 2; ++c) {
                        ull snd = b3 ? acc[i][c] : acc[i + 4][c];
                        ull rcv = __shfl_xor_sync(0xffffffffu, snd, 8);
                        ull kp  = b3 ? acc[i + 4][c] : acc[i][c];
                        acc[i][c] = add2(kp, rcv);
                    }
                #pragma unroll
                for (int i = 0; i < 2; ++i)
                    #pragma unroll
                    for (int c = 0; c < 2; ++c) {
                        ull snd = b2 ? acc[i][c] : acc[i + 2][c];
                        ull rcv = __shfl_xor_sync(0xffffffffu, snd, 4);
                        ull kp  = b2 ? acc[i + 2][c] : acc[i][c];
                        acc[i][c] = add2(kp, rcv);
                    }
                #pragma unroll
                for (int c = 0; c < 2; ++c) {
                    ull snd = b1 ? acc[0][c] : acc[1][c];
                    ull rcv = __shfl_xor_sync(0xffffffffu, snd, 2);
                    ull kp  = b1 ? acc[1][c] : acc[0][c];
                    acc[0][c] = add2(kp, rcv);
                }
                ull fin;
                {
                    ull snd = b0 ? acc[0][0] : acc[0][1];
                    ull rcv = __shfl_xor_sync(0xffffffffu, snd, 1);
                    ull kp  = b0 ? acc[0][1] : acc[0][0];
                    fin = add2(kp, rcv);
                }

                float2 vv = unpack2(fin);
                float2 bb = *reinterpret_cast<const float2*>(&s->b_h[L][fcol]);
                float2 rr;
                rr.x = tanh_fast(vv.x + bb.x);
                rr.y = tanh_fast(vv.y + bb.y);
                *reinterpret_cast<float2*>(&hout[fco]) = rr;
                __syncthreads();
            }

            // ---- fused epilogue + next-stage input (warps 0..6) ----
            if (w < NROWS) {
                const float* hr = &s->h[1][w * HSTRIDE];
                float hv0 = hr[sw0], hv1 = hr[sw1], hv2 = hr[sw2], hv3 = hr[sw3];
                float dots[S_DIM];
                #pragma unroll
                for (int o = 0; o < S_DIM; ++o) {
                    float p = hv0 * s->W_out_t[o][lane]
                            + hv1 * s->W_out_t[o][lane + 32]
                            + hv2 * s->W_out_t[o][lane + 64]
                            + hv3 * s->W_out_t[o][lane + 96];
                    #pragma unroll
                    for (int off = 16; off; off >>= 1)
                        p += __shfl_xor_sync(0xffffffffu, p, off);  // allreduce: valid on all lanes
                    dots[o] = p;
                }
                float msel = (st == 0) ? m0 : ((st == 3) ? m1 : mm);
                float wg   = (st == 0 || st == 3) ? dt6 : dt3;
                float yca[S_DIM] = {yc0, yc1, yc2, yc3, yc4, yc5};
                float nyc[S_DIM];
                if (st < 3) {
                    float cn = (st < 2) ? 0.5f * dt : dt;
                    #pragma unroll
                    for (int o = 0; o < S_DIM; ++o) {
                        float kv = dots[o] + s->b_out[o] + ode_comp(o, yca, msel);
                        float av = s->acc[w][o] + wg * kv;
                        if (lane == 0) s->acc[w][o] = av;
                        nyc[o] = s->y[w][o] + cn * kv;
                    }
                } else {
                    #pragma unroll
                    for (int o = 0; o < S_DIM; ++o) {
                        float kv = dots[o] + s->b_out[o] + ode_comp(o, yca, msel);
                        float av = s->acc[w][o] + wg * kv;
                        nyc[o] = av;
                        if (lane == 0) {
                            s->acc[w][o] = av;
                            s->y[w][o] = av;
                            if (w < nr)
                                out[(size_t)(base + w) * T_DIM * S_DIM
                                    + (size_t)(t + 1) * S_DIM + o] = av;
                        }
                    }
                }
                yc0 = nyc[0]; yc1 = nyc[1]; yc2 = nyc[2];
                yc3 = nyc[3]; yc4 = nyc[4]; yc5 = nyc[5];
                if (st < 3) {
                    float ts_n = (st == 2) ? T1 : tm;
                    float vs_n = (st == 2) ? v1 : vm;
                    input_row(s, w, lane, yc0, yc1, yc2, yc3, yc4, yc5, ts_n, vs_n);
                }
            }
            __syncthreads();
        } // stages
    } // steps
}

extern "C" void kernel_launch(void* const* d_in, const int* in_sizes, int n_in,
                              void* d_out, int out_size) {
    const float* init   = (const float*)d_in[0];
    const float* t_span = (const float*)d_in[1];
    const float* meal   = (const float*)d_in[2];
    const float* tvns   = (const float*)d_in[3];
    const float* W_in   = (const float*)d_in[4];
    const float* b_in   = (const float*)d_in[5];
    const float* W_h    = (const float*)d_in[6];
    const float* b_h    = (const float*)d_in[7];
    const float* W_out  = (const float*)d_in[8];
    const float* b_out  = (const float*)d_in[9];
    float* out = (float*)d_out;

    const size_t smem_bytes = sizeof(Smem);  // ~206 KB
    cudaFuncSetAttribute(hybrid_ode_kernel,
                         cudaFuncAttributeMaxDynamicSharedMemorySize,
                         (int)smem_bytes);

    hybrid_ode_kernel<<<GRID, NTHREADS, smem_bytes>>>(
        init, t_span, meal, tvns, W_in, b_in, W_h, b_h, W_out, b_out, out);
}

// round 16
// speedup vs baseline: 1.0340x; 1.0122x over previous
#include <cuda_runtime.h>

// HybridODENN: B=1024, T=256, H=128, 3 hidden layers, S=6
#define B_DIM 1024
#define T_DIM 256
#define H_DIM 128
#define S_DIM 6
#define ROWS 8                    // array sizing (pad row 7)
#define NROWS 7                   // real rows per CTA
#define GRID 147                  // 146 x 7 + 1 x 2 = 1024
#define NTHREADS 512
#define HSTRIDE 136

// ODE constants
#define C_A_GI 0.01f
#define C_K_I  0.1f
#define C_RHO  0.05f
#define C_EMAX 2.0f
#define C_EC50 5.0f
#define C_VMAX 1.0f
#define C_KM   100.0f
#define C_KL   0.2f

typedef unsigned long long ull;

#define FFMA2(d, a, b) asm("fma.rn.f32x2 %0, %1, %2, %0;" : "+l"(d) : "l"(a), "l"(b))

__device__ __forceinline__ ull add2(ull a, ull b) {
    ull d; asm("add.rn.f32x2 %0, %1, %2;" : "=l"(d) : "l"(a), "l"(b)); return d;
}
__device__ __forceinline__ float2 unpack2(ull v) {
    float lo, hi;
    asm("mov.b64 {%0, %1}, %2;" : "=f"(lo), "=f"(hi) : "l"(v));
    return make_float2(lo, hi);
}
__device__ __forceinline__ ull dup2f(float x) {
    ull d; asm("mov.b64 %0, {%1, %1};" : "=l"(d) : "f"(x)); return d;
}
// fast tanh: 1 - 2/(e^{2x}+1), ~1e-7 rel err
__device__ __forceinline__ float tanh_fast(float x) {
    float e;
    asm("ex2.approx.f32 %0, %1;" : "=f"(e) : "f"(x * 2.8853900817779268f));
    float r;
    asm("rcp.approx.f32 %0, %1;" : "=f"(r) : "f"(e + 1.0f));
    return fmaf(-2.0f, r, 1.0f);
}
// h column swizzle: chunk ck = c>>2 -> ck ^ (ck>>3), keep (c&3)
__device__ __forceinline__ int hswz(int c) {
    int ck = c >> 2;
    int ckp = ck ^ (ck >> 3);
    return ckp * 4 + (c & 3);
}

struct __align__(16) Smem {
    // W_h[l][k][ g'*4 + (c&3) ], g' = (c>>2) ^ ((k>>3)&15)
    float W_h[3][H_DIM][H_DIM];   // 192 KB
    float W_in[9][H_DIM];         // row 4 holds W_in[4]+W_in[7] (y3 appears twice)
    float W_out_t[S_DIM][H_DIM];
    float b_in[H_DIM];
    float b_h[3][H_DIM];
    float b_out[8];
    float h[2][ROWS * HSTRIDE];   // swizzled cols + padded rows
    float y[ROWS][S_DIM];
    float acc[ROWS][S_DIM];
};

__device__ __forceinline__ float ode_comp(int o, const float* y, float m) {
    float G = y[0], I = y[1], N = y[2], L = y[3], GE = y[4], F = y[5];
    switch (o) {
        case 0: return -C_A_GI * I * G + C_RHO * GE;
        case 1: return __fdividef(C_VMAX * G, C_KM + G)
                       * (1.0f + C_EMAX * __fdividef(L, C_EC50 + L)) - C_K_I * I;
        case 2: return -C_RHO * N;
        case 3: return C_RHO * GE - C_KL * L;
        case 4: return m - C_RHO * GE;
        default: return -C_A_GI * I * F;
    }
}

// fused input layer: warp owns row r; lane computes cols [lane*4, lane*4+4)
// (W_in[4] has been pre-folded with W_in[7]: y3 coefficient combined)
__device__ __forceinline__ void input_row(Smem* s, int r, int lane,
                                          float y0, float y1, float y2,
                                          float y3, float y4, float y5,
                                          float ts, float vs)
{
    int jb = lane * 4;
    int so = r * HSTRIDE + ((lane ^ (lane >> 3)) * 4);   // hswz of chunk=lane
    float4 bb = *reinterpret_cast<const float4*>(&s->b_in[jb]);
    float4 q0 = *reinterpret_cast<const float4*>(&s->W_in[0][jb]);
    float4 q1 = *reinterpret_cast<const float4*>(&s->W_in[1][jb]);
    float4 q2 = *reinterpret_cast<const float4*>(&s->W_in[2][jb]);
    float4 q3 = *reinterpret_cast<const float4*>(&s->W_in[3][jb]);
    float4 q4 = *reinterpret_cast<const float4*>(&s->W_in[4][jb]);   // folded +W_in[7]
    float4 q5 = *reinterpret_cast<const float4*>(&s->W_in[5][jb]);
    float4 q6 = *reinterpret_cast<const float4*>(&s->W_in[6][jb]);
    float4 q8 = *reinterpret_cast<const float4*>(&s->W_in[8][jb]);
    float4 a;
    a.x = bb.x + ts*q0.x + y0*q1.x + y1*q2.x + y2*q3.x + y3*q4.x + y4*q5.x + y5*q6.x + vs*q8.x;
    a.y = bb.y + ts*q0.y + y0*q1.y + y1*q2.y + y2*q3.y + y3*q4.y + y4*q5.y + y5*q6.y + vs*q8.y;
    a.z = bb.z + ts*q0.z + y0*q1.z + y1*q2.z + y2*q3.z + y3*q4.z + y4*q5.z + y5*q6.z + vs*q8.z;
    a.w = bb.w + ts*q0.w + y0*q1.w + y1*q2.w + y2*q3.w + y3*q4.w + y4*q5.w + y5*q6.w + vs*q8.w;
    float4 o4;
    o4.x = tanh_fast(a.x); o4.y = tanh_fast(a.y);
    o4.z = tanh_fast(a.z); o4.w = tanh_fast(a.w);
    *reinterpret_cast<float4*>(&s->h[0][so]) = o4;
}

__global__ void __launch_bounds__(NTHREADS, 1)
hybrid_ode_kernel(const float* __restrict__ init,
                  const float* __restrict__ t_span,
                  const float* __restrict__ meal,
                  const float* __restrict__ tvns,
                  const float* __restrict__ gW_in,
                  const float* __restrict__ gb_in,
                  const float* __restrict__ gW_h,
                  const float* __restrict__ gb_h,
                  const float* __restrict__ gW_out,
                  const float* __restrict__ gb_out,
                  float* __restrict__ out)
{
    extern __shared__ __align__(16) char smem_raw[];
    Smem* s = reinterpret_cast<Smem*>(smem_raw);

    const int tid  = threadIdx.x;
    const int cta  = blockIdx.x;
    const int base = cta * NROWS;
    const int nr   = (B_DIM - base < NROWS) ? (B_DIM - base) : NROWS;

    // ---- one-time weight staging (W_h col-group XOR swizzle) ----
    for (int i = tid; i < 3 * H_DIM * H_DIM; i += NTHREADS) {
        int l = i >> 14;
        int rem = i & 16383;
        int k = rem >> 7, c = rem & 127;
        int gp = (c >> 2) ^ ((k >> 3) & 15);
        s->W_h[l][k][gp * 4 + (c & 3)] = gW_h[i];
    }
    for (int i = tid; i < 9 * H_DIM; i += NTHREADS) {
        int row = i >> 7;
        float v = gW_in[i];
        if (row == 4) v += gW_in[7 * H_DIM + (i & 127)];   // fold y3's second term
        (&s->W_in[0][0])[i] = v;
    }
    for (int i = tid; i < H_DIM; i += NTHREADS) s->b_in[i] = gb_in[i];
    for (int i = tid; i < 3 * H_DIM; i += NTHREADS) (&s->b_h[0][0])[i] = gb_h[i];
    for (int i = tid; i < H_DIM * S_DIM; i += NTHREADS) {
        int k = i / S_DIM, o = i % S_DIM;
        s->W_out_t[o][k] = gW_out[i];
    }
    if (tid < S_DIM) (&s->b_out[0])[tid] = gb_out[tid];

    // ---- GEMM mapping (r10/r11-proven) ----
    const int w    = tid >> 5;
    const int lane = tid & 31;
    const int ks   = lane & 15;
    const int cg   = lane >> 4;
    const int c0   = w * 8 + cg * 4;
    const int gexp = (((w << 1) + cg) ^ ks) << 2;
    int hco0, hco1;
    {
        int ck0 = 2 * ks, ck1 = 2 * ks + 1;
        hco0 = (ck0 ^ (ck0 >> 3)) * 4;
        hco1 = (ck1 ^ (ck1 >> 3)) * 4;
    }
    const int frow = ((ks >> 3) & 1) * 4 + ((ks >> 2) & 1) * 2 + ((ks >> 1) & 1);
    const int fcol = c0 + 2 * (ks & 1);
    const int fco  = frow * HSTRIDE + hswz(fcol);
    const bool b3 = (ks & 8) != 0, b2 = (ks & 4) != 0, b1 = (ks & 2) != 0, b0 = (ks & 1) != 0;
    const int sw0 = hswz(lane), sw1 = hswz(lane + 32), sw2 = hswz(lane + 64), sw3 = hswz(lane + 96);

    // ---- register-resident ycur (warp w < NROWS owns batch row w) ----
    float yc0 = 0.f, yc1 = 0.f, yc2 = 0.f, yc3 = 0.f, yc4 = 0.f, yc5 = 0.f;
    if (w < NROWS) {
        int rr = (w < nr) ? w : 0;
        const float* ip = init + (size_t)(base + rr) * S_DIM;
        yc0 = ip[0]; yc1 = ip[1]; yc2 = ip[2];
        yc3 = ip[3]; yc4 = ip[4]; yc5 = ip[5];
        if (lane == 0) {
            s->y[w][0] = yc0; s->y[w][1] = yc1; s->y[w][2] = yc2;
            s->y[w][3] = yc3; s->y[w][4] = yc4; s->y[w][5] = yc5;
            s->acc[w][0] = yc0; s->acc[w][1] = yc1; s->acc[w][2] = yc2;
            s->acc[w][3] = yc3; s->acc[w][4] = yc4; s->acc[w][5] = yc5;
            if (w < nr) {
                float* op = out + (size_t)(base + w) * T_DIM * S_DIM;
                op[0] = yc0; op[1] = yc1; op[2] = yc2;
                op[3] = yc3; op[4] = yc4; op[5] = yc5;
            }
        }
    }
    __syncthreads();

    // ---- persistent W registers: k-chunk 0, all 3 layers ----
    ulonglong2 wp0[4], wp1[4], wp2[4];
    #pragma unroll
    for (int i = 0; i < 4; ++i) {
        wp0[i] = *reinterpret_cast<const ulonglong2*>(&s->W_h[0][ks * 8 + i][0] + gexp);
        wp1[i] = *reinterpret_cast<const ulonglong2*>(&s->W_h[1][ks * 8 + i][0] + gexp);
        wp2[i] = *reinterpret_cast<const ulonglong2*>(&s->W_h[2][ks * 8 + i][0] + gexp);
    }

    for (int t = 0; t < T_DIM - 1; ++t) {
        const float T0 = t_span[t], T1 = t_span[t + 1];
        const float dt = T1 - T0;
        const float tm = T0 + 0.5f * dt;
        const float dt6 = dt * (1.0f / 6.0f), dt3 = dt * (1.0f / 3.0f);

        float m0 = 0.f, mm = 0.f, m1 = 0.f, v1 = 0.f, vm = 0.f;
        if (w < NROWS) {
            int rr = (w < nr) ? w : 0;
            size_t ri = (size_t)(base + rr) * T_DIM + t;
            float M0 = meal[ri], M1 = meal[ri + 1];
            float V0 = tvns[ri], V1 = tvns[ri + 1];
            m0 = M0; m1 = M1; mm = 0.5f * (M0 + M1);
            v1 = V1; vm = 0.5f * (V0 + V1);
            input_row(s, w, lane, yc0, yc1, yc2, yc3, yc4, yc5, T0, V0);
        }
        __syncthreads();

        #pragma unroll
        for (int st = 0; st < 4; ++st) {
            // ---- 3 hidden layers (r11 GEMM: per-layer wv load, wp persistent) ----
            #pragma unroll
            for (int L = 0; L < 3; ++L) {
                const float* hin  = s->h[L & 1];
                float*       hout = s->h[(L & 1) ^ 1];
                const float* wbase = &s->W_h[L][ks * 8][0] + gexp;

                ulonglong2 wv[4];
                #pragma unroll
                for (int i = 0; i < 4; ++i)
                    wv[i] = *reinterpret_cast<const ulonglong2*>(wbase + (4 + i) * H_DIM);

                ull acc[8][2];
                #pragma unroll
                for (int r = 0; r < 8; ++r) { acc[r][0] = 0ull; acc[r][1] = 0ull; }

                #pragma unroll
                for (int r = 0; r < NROWS; ++r) {
                    float4 ha = *reinterpret_cast<const float4*>(hin + r * HSTRIDE + hco0);
                    float4 hb = *reinterpret_cast<const float4*>(hin + r * HSTRIDE + hco1);
                    ull d;
                    if (L == 0) {
                        d = dup2f(ha.x); FFMA2(acc[r][0], d, wp0[0].x); FFMA2(acc[r][1], d, wp0[0].y);
                        d = dup2f(ha.y); FFMA2(acc[r][0], d, wp0[1].x); FFMA2(acc[r][1], d, wp0[1].y);
                        d = dup2f(ha.z); FFMA2(acc[r][0], d, wp0[2].x); FFMA2(acc[r][1], d, wp0[2].y);
                        d = dup2f(ha.w); FFMA2(acc[r][0], d, wp0[3].x); FFMA2(acc[r][1], d, wp0[3].y);
                    } else if (L == 1) {
                        d = dup2f(ha.x); FFMA2(acc[r][0], d, wp1[0].x); FFMA2(acc[r][1], d, wp1[0].y);
                        d = dup2f(ha.y); FFMA2(acc[r][0], d, wp1[1].x); FFMA2(acc[r][1], d, wp1[1].y);
                        d = dup2f(ha.z); FFMA2(acc[r][0], d, wp1[2].x); FFMA2(acc[r][1], d, wp1[2].y);
                        d = dup2f(ha.w); FFMA2(acc[r][0], d, wp1[3].x); FFMA2(acc[r][1], d, wp1[3].y);
                    } else {
                        d = dup2f(ha.x); FFMA2(acc[r][0], d, wp2[0].x); FFMA2(acc[r][1], d, wp2[0].y);
                        d = dup2f(ha.y); FFMA2(acc[r][0], d, wp2[1].x); FFMA2(acc[r][1], d, wp2[1].y);
                        d = dup2f(ha.z); FFMA2(acc[r][0], d, wp2[2].x); FFMA2(acc[r][1], d, wp2[2].y);
                        d = dup2f(ha.w); FFMA2(acc[r][0], d, wp2[3].x); FFMA2(acc[r][1], d, wp2[3].y);
                    }
                    d = dup2f(hb.x); FFMA2(acc[r][0], d, wv[0].x); FFMA2(acc[r][1], d, wv[0].y);
                    d = dup2f(hb.y); FFMA2(acc[r][0], d, wv[1].x); FFMA2(acc[r][1], d, wv[1].y);
                    d = dup2f(hb.z); FFMA2(acc[r][0], d, wv[2].x); FFMA2(acc[r][1], d, wv[2].y);
                    d = dup2f(hb.w); FFMA2(acc[r][0], d, wv[3].x); FFMA2(acc[r][1], d, wv[3].y);
                }

                // ---- 4-round send-select fold over 16-way k-split (acc[7] = 0) ----
                #pragma unroll
                for (int i = 0; i < 4; ++i)
                    #pragma unroll
                    for (int c = 0; c < 2; ++c) {
                        ull snd = b3 ? acc[i][c] : acc[i + 4][c];
                        ull rcv = __shfl_xor_sync(0xffffffffu, snd, 8);
                        ull kp  = b3 ? acc[i + 4][c] : acc[i][c];
                        acc[i][c] = add2(kp, rcv);
                    }
                #pragma unroll
                for (int i = 0; i < 2; ++i)
                    #pragma unroll
                    for (int c = 0; c < 2; ++c) {
                        ull snd = b2 ? acc[i][c] : acc[i + 2][c];
                        ull rcv = __shfl_xor_sync(0xffffffffu, snd, 4);
                        ull kp  = b2 ? acc[i + 2][c] : acc[i][c];
                        acc[i][c] = add2(kp, rcv);
                    }
                #pragma unroll
                for (int c = 0; c < 2; ++c) {
                    ull snd = b1 ? acc[0][c] : acc[1][c];
                    ull rcv = __shfl_xor_sync(0xffffffffu, snd, 2);
                    ull kp  = b1 ? acc[1][c] : acc[0][c];
                    acc[0][c] = add2(kp, rcv);
                }
                ull fin;
                {
                    ull snd = b0 ? acc[0][0] : acc[0][1];
                    ull rcv = __shfl_xor_sync(0xffffffffu, snd, 1);
                    ull kp  = b0 ? acc[0][1] : acc[0][0];
                    fin = add2(kp, rcv);
                }

                float2 vv = unpack2(fin);
                float2 bb = *reinterpret_cast<const float2*>(&s->b_h[L][fcol]);
                float2 rr;
                rr.x = tanh_fast(vv.x + bb.x);
                rr.y = tanh_fast(vv.y + bb.y);
                *reinterpret_cast<float2*>(&hout[fco]) = rr;
                __syncthreads();
            }

            // ---- fused epilogue + next-stage input (warps 0..6) ----
            if (w < NROWS) {
                const float* hr = &s->h[1][w * HSTRIDE];
                float hv0 = hr[sw0], hv1 = hr[sw1], hv2 = hr[sw2], hv3 = hr[sw3];
                float dots[S_DIM];
                #pragma unroll
                for (int o = 0; o < S_DIM; ++o) {
                    float p = hv0 * s->W_out_t[o][lane]
                            + hv1 * s->W_out_t[o][lane + 32]
                            + hv2 * s->W_out_t[o][lane + 64]
                            + hv3 * s->W_out_t[o][lane + 96];
                    #pragma unroll
                    for (int off = 16; off; off >>= 1)
                        p += __shfl_xor_sync(0xffffffffu, p, off);  // allreduce: valid on all lanes
                    dots[o] = p;
                }
                float msel = (st == 0) ? m0 : ((st == 3) ? m1 : mm);
                float wg   = (st == 0 || st == 3) ? dt6 : dt3;
                float yca[S_DIM] = {yc0, yc1, yc2, yc3, yc4, yc5};
                float nyc[S_DIM];
                if (st < 3) {
                    float cn = (st < 2) ? 0.5f * dt : dt;
                    #pragma unroll
                    for (int o = 0; o < S_DIM; ++o) {
                        float kv = dots[o] + s->b_out[o] + ode_comp(o, yca, msel);
                        float av = s->acc[w][o] + wg * kv;
                        if (lane == 0) s->acc[w][o] = av;
                        nyc[o] = s->y[w][o] + cn * kv;
                    }
                } else {
                    #pragma unroll
                    for (int o = 0; o < S_DIM; ++o) {
                        float kv = dots[o] + s->b_out[o] + ode_comp(o, yca, msel);
                        float av = s->acc[w][o] + wg * kv;
                        nyc[o] = av;
                        if (lane == 0) {
                            s->acc[w][o] = av;
                            s->y[w][o] = av;
                            if (w < nr)
                                out[(size_t)(base + w) * T_DIM * S_DIM
                                    + (size_t)(t + 1) * S_DIM + o] = av;
                        }
                    }
                }
                yc0 = nyc[0]; yc1 = nyc[1]; yc2 = nyc[2];
                yc3 = nyc[3]; yc4 = nyc[4]; yc5 = nyc[5];
                if (st < 3) {
                    float ts_n = (st == 2) ? T1 : tm;
                    float vs_n = (st == 2) ? v1 : vm;
                    input_row(s, w, lane, yc0, yc1, yc2, yc3, yc4, yc5, ts_n, vs_n);
                }
            }
            __syncthreads();
        } // stages
    } // steps
}

extern "C" void kernel_launch(void* const* d_in, const int* in_sizes, int n_in,
                              void* d_out, int out_size) {
    const float* init   = (const float*)d_in[0];
    const float* t_span = (const float*)d_in[1];
    const float* meal   = (const float*)d_in[2];
    const float* tvns   = (const float*)d_in[3];
    const float* W_in   = (const float*)d_in[4];
    const float* b_in   = (const float*)d_in[5];
    const float* W_h    = (const float*)d_in[6];
    const float* b_h    = (const float*)d_in[7];
    const float* W_out  = (const float*)d_in[8];
    const float* b_out  = (const float*)d_in[9];
    float* out = (float*)d_out;

    const size_t smem_bytes = sizeof(Smem);  // ~206 KB
    cudaFuncSetAttribute(hybrid_ode_kernel,
                         cudaFuncAttributeMaxDynamicSharedMemorySize,
                         (int)smem_bytes);

    hybrid_ode_kernel<<<GRID, NTHREADS, smem_bytes>>>(
        init, t_span, meal, tvns, W_in, b_in, W_h, b_h, W_out, b_out, out);
}